// round 4
// baseline (speedup 1.0000x reference)
#include <cuda_runtime.h>
#include <cstdint>

#define NPTS 500000
#define KOFF 27
#define TILE 128
#define NTH  256

// ---- shared memory layout (bytes) ----
#define SM_NBR  0          // 128*27*4 = 13824
#define SM_B    13824      // 2 * 64*64*4 = 32768 -> 46592
#define SM_A    46592      // 2 * 128*256 = 65536 -> 112128
#define SM_BIAS 112128     // 256
#define SM_TOTAL 112384

// ---- device scratch (no allocations allowed) ----
static __device__ float g_x[(size_t)NPTS * 64];     // layer-1 activations
static __device__ float g_wt[KOFF * 64 * 64];       // tf32-rounded, XOR-swizzled W

// ---- helpers ----
__device__ __forceinline__ uint32_t smem_u32(const void* p) {
    uint32_t a;
    asm("{ .reg .u64 t; cvta.to.shared.u64 t, %1; cvt.u32.u64 %0, t; }" : "=r"(a) : "l"(p));
    return a;
}
__device__ __forceinline__ void cp16(uint32_t d, const void* s) {
    asm volatile("cp.async.cg.shared.global [%0], [%1], 16;" :: "r"(d), "l"(s) : "memory");
}
__device__ __forceinline__ void cp16z(uint32_t d, const void* s, unsigned sz) {
    asm volatile("cp.async.cg.shared.global [%0], [%1], 16, %2;" :: "r"(d), "l"(s), "r"(sz) : "memory");
}
__device__ __forceinline__ uint32_t f2tf(float f) {
    uint32_t u;
    asm("cvt.rna.tf32.f32 %0, %1;" : "=r"(u) : "f"(f));
    return u;
}
__device__ __forceinline__ float lds_f(uint32_t a) {
    float v;
    asm volatile("ld.shared.f32 %0, [%1];" : "=f"(v) : "r"(a));
    return v;
}
__device__ __forceinline__ uint32_t lds_u(uint32_t a) {
    uint32_t v;
    asm volatile("ld.shared.b32 %0, [%1];" : "=r"(v) : "r"(a));
    return v;
}
__device__ __forceinline__ void mma8(float* c, const uint32_t* a, const uint32_t* b) {
    asm volatile(
        "mma.sync.aligned.m16n8k8.row.col.f32.tf32.tf32.f32 "
        "{%0,%1,%2,%3}, {%4,%5,%6,%7}, {%8,%9}, {%0,%1,%2,%3};"
        : "+f"(c[0]), "+f"(c[1]), "+f"(c[2]), "+f"(c[3])
        : "r"(a[0]), "r"(a[1]), "r"(a[2]), "r"(a[3]), "r"(b[0]), "r"(b[1]));
}

// ---- prep: round W to tf32; XOR-swizzle columns at 8-float granularity ----
// W layout [k][cin][cout] == mma B (k x n): no transpose. Swizzle makes the
// B-fragment LDS pattern bank-conflict-free: bank = q | ((nt^rl)<<3).
__global__ void prep_w_kernel(const float* __restrict__ W) {
    int i = blockIdx.x * 256 + threadIdx.x;
    if (i >= KOFF * 64 * 64) return;
    int k  = i >> 12;
    int rem = i & 4095;
    int ci = rem >> 6;
    int n  = rem & 63;
    ((uint32_t*)g_wt)[k * 4096 + ci * 64 + (n ^ ((ci & 3) << 3))] = f2tf(W[i]);
}

// ---- main conv layer ----
__global__ void __launch_bounds__(NTH, 2)
conv_layer_kernel(const float* __restrict__ feats,
                  const float* __restrict__ bias,
                  const float* __restrict__ alpha,
                  const int*   __restrict__ nbr,
                  float*       __restrict__ out_final,
                  int layer)
{
    extern __shared__ __align__(16) char smem[];
    const int tid = threadIdx.x;
    const int tile_base = blockIdx.x * TILE;
    const uint32_t sb = smem_u32(smem);

    const float* in  = (layer == 0) ? feats : (const float*)g_x;
    float*       out = (layer == 0) ? (float*)g_x : out_final;

    // stage neighbor indices (contiguous block) + bias
    int* nbr_s = (int*)smem;
    {
        int vr = NPTS - tile_base; if (vr > TILE) vr = TILE;
        int total = vr * KOFF;
        const int* ng = nbr + (size_t)tile_base * KOFF;
        for (int f = tid; f < TILE * KOFF; f += NTH) nbr_s[f] = (f < total) ? ng[f] : -1;
        if (tid < 64) ((float*)(smem + SM_BIAS))[tid] = bias[tid];
    }
    __syncthreads();

    const int row_g = tid >> 1;      // gather row 0..127
    const int halfg = tid & 1;       // which 8-chunk half of the 256B row

    auto prefetch = [&](int buf, int k) {
        // B: linear 16KB copy of pre-swizzled W[k] (exactly 1024 x 16B)
        const float* ws = g_wt + k * 4096;
        uint32_t bd = sb + SM_B + buf * 16384;
        #pragma unroll
        for (int i = 0; i < 4; i++) {
            int e = tid + i * NTH;
            cp16(bd + e * 16, ws + e * 4);
        }
        // A: gather 128 rows x 256B, XOR-swizzled 16B chunks, zero-fill invalid taps
        int idx = nbr_s[row_g * KOFF + k];
        const float* sr = in + (size_t)(idx < 0 ? 0 : idx) * 64;
        uint32_t ad = sb + SM_A + buf * 32768 + row_g * 256;
        unsigned sz = (idx >= 0) ? 16u : 0u;
        int r7 = row_g & 7;
        #pragma unroll
        for (int j = 0; j < 8; j++) {
            int c = halfg * 8 + j;
            cp16z(ad + ((c ^ r7) << 4), sr + c * 4, sz);
        }
        asm volatile("cp.async.commit_group;" ::: "memory");
    };

    const int lane = tid & 31, w = tid >> 5;
    const int wm = w & 3, wn = w >> 2;      // warp grid 4(m) x 2(n)
    const int q = lane >> 2, rl = lane & 3;

    float acc[2][4][4];
    #pragma unroll
    for (int i = 0; i < 2; i++)
        #pragma unroll
        for (int j = 0; j < 4; j++)
            #pragma unroll
            for (int l = 0; l < 4; l++) acc[i][j][l] = 0.f;

    // per-thread A row byte offsets (local rows); row&7 == q for all of them
    uint32_t arow[2][2];
    #pragma unroll
    for (int mt = 0; mt < 2; mt++) {
        int r = wm * 32 + mt * 16 + q;
        arow[mt][0] = (uint32_t)(r * 256 + rl * 4);
        arow[mt][1] = arow[mt][0] + 8 * 256;
    }
    // B per-thread base: row rl (256B rows), col chunk wn*32, lane word q
    const uint32_t bbase = (uint32_t)(rl * 256 + wn * 128 + q * 4);

    prefetch(0, 0);

    #pragma unroll 1
    for (int k = 0; k < KOFF; k++) {
        const int cur = k & 1;
        if (k + 1 < KOFF) {
            prefetch(1 - cur, k + 1);
            asm volatile("cp.async.wait_group 1;" ::: "memory");
        } else {
            asm volatile("cp.async.wait_group 0;" ::: "memory");
        }
        __syncthreads();   // all threads' cp.async for 'cur' visible

        const uint32_t Ab = sb + SM_A + cur * 32768;
        const uint32_t Bb = sb + SM_B + cur * 16384 + bbase;
        #pragma unroll
        for (int kc = 0; kc < 8; kc++) {
            uint32_t a[2][4];
            const uint32_t o0 = (uint32_t)((((kc * 2)    ) ^ q) << 4);
            const uint32_t o1 = (uint32_t)((((kc * 2) + 1) ^ q) << 4);
            #pragma unroll
            for (int mt = 0; mt < 2; mt++) {
                a[mt][0] = f2tf(lds_f(Ab + arow[mt][0] + o0));
                a[mt][1] = f2tf(lds_f(Ab + arow[mt][1] + o0));
                a[mt][2] = f2tf(lds_f(Ab + arow[mt][0] + o1));
                a[mt][3] = f2tf(lds_f(Ab + arow[mt][1] + o1));
            }
            // B rows kc*8+rl and kc*8+4+rl; column XOR-deswizzle: (nt^rl) chunk
            uint32_t b[4][2];
            const uint32_t bk = Bb + (uint32_t)(kc * 2048);
            #pragma unroll
            for (int nt = 0; nt < 4; nt++) {
                uint32_t co = (uint32_t)((nt ^ rl) * 32);
                b[nt][0] = lds_u(bk + co);
                b[nt][1] = lds_u(bk + 1024 + co);
            }
            #pragma unroll
            for (int mt = 0; mt < 2; mt++)
                #pragma unroll
                for (int nt = 0; nt < 4; nt++)
                    mma8(acc[mt][nt], a[mt], b[nt]);
        }
        __syncthreads();   // compute done before this buffer is overwritten
    }

    // ---- epilogue: bias (+ residual) + PReLU, float2 stores ----
    const float av = alpha[0];
    const float* bs = (const float*)(smem + SM_BIAS);
    #pragma unroll
    for (int mt = 0; mt < 2; mt++) {
        #pragma unroll
        for (int hh = 0; hh < 2; hh++) {
            int np = tile_base + wm * 32 + mt * 16 + q + hh * 8;
            if (np < NPTS) {
                float* orow = out + (size_t)np * 64;
                const float* frow = feats + (size_t)np * 64;
                #pragma unroll
                for (int nt = 0; nt < 4; nt++) {
                    int cc = wn * 32 + nt * 8 + 2 * rl;
                    float v0 = acc[mt][nt][hh * 2 + 0] + bs[cc];
                    float v1 = acc[mt][nt][hh * 2 + 1] + bs[cc + 1];
                    if (layer == 1) { v0 += frow[cc]; v1 += frow[cc + 1]; }
                    v0 = v0 >= 0.f ? v0 : av * v0;
                    v1 = v1 >= 0.f ? v1 : av * v1;
                    float2 vv; vv.x = v0; vv.y = v1;
                    *(float2*)(orow + cc) = vv;
                }
            }
        }
    }
}

// ---- launch ----
extern "C" void kernel_launch(void* const* d_in, const int* in_sizes, int n_in,
                              void* d_out, int out_size)
{
    const float* feats = (const float*)d_in[0];
    const float* W1    = (const float*)d_in[1];
    const float* b1    = (const float*)d_in[2];
    const float* a1    = (const float*)d_in[3];
    const float* W2    = (const float*)d_in[4];
    const float* b2    = (const float*)d_in[5];
    const float* a2    = (const float*)d_in[6];
    const int*   nbr   = (const int*)d_in[7];
    float* out = (float*)d_out;

    cudaFuncSetAttribute(conv_layer_kernel, cudaFuncAttributeMaxDynamicSharedMemorySize, SM_TOTAL);

    const int ntiles = (NPTS + TILE - 1) / TILE;
    const int prep_blocks = (KOFF * 64 * 64 + 255) / 256;

    prep_w_kernel<<<prep_blocks, 256>>>(W1);
    conv_layer_kernel<<<ntiles, NTH, SM_TOTAL>>>(feats, b1, a1, nbr, out, 0);
    prep_w_kernel<<<prep_blocks, 256>>>(W2);
    conv_layer_kernel<<<ntiles, NTH, SM_TOTAL>>>(feats, b2, a2, nbr, out, 1);
}

// round 6
// speedup vs baseline: 1.9595x; 1.9595x over previous
#include <cuda_runtime.h>
#include <cuda_fp16.h>
#include <cstdint>

#define NPTS 500000
#define KOFF 27
#define TILE 128
#define NTH  256

// ---- shared memory layout (bytes) ----
#define SM_NBR  0            // 128*27*4 = 13824
#define SM_B    13824        // 2 * 8192  -> 30208
#define SM_A    30208        // 2 * 16384 -> 62976
#define SM_BIAS 62976        // 256
#define SM_TOTAL 63232

// ---- device scratch (no allocations allowed) ----
static __device__ __align__(16) __half g_xh[(size_t)NPTS * 64];  // layer-1 activations (f16)
static __device__ __align__(16) __half g_fh[(size_t)NPTS * 64];  // feats converted to f16
static __device__ uint32_t g_wt[KOFF * 32 * 64];                 // W packed half2(k,k+1), swizzled

// ---- helpers ----
__device__ __forceinline__ uint32_t smem_u32(const void* p) {
    uint32_t a;
    asm("{ .reg .u64 t; cvta.to.shared.u64 t, %1; cvt.u32.u64 %0, t; }" : "=r"(a) : "l"(p));
    return a;
}
__device__ __forceinline__ void cp16(uint32_t d, const void* s) {
    asm volatile("cp.async.cg.shared.global [%0], [%1], 16;" :: "r"(d), "l"(s) : "memory");
}
__device__ __forceinline__ void cp16z(uint32_t d, const void* s, unsigned sz) {
    asm volatile("cp.async.cg.shared.global [%0], [%1], 16, %2;" :: "r"(d), "l"(s), "r"(sz) : "memory");
}
__device__ __forceinline__ uint32_t lds_u(uint32_t a) {
    uint32_t v;
    asm volatile("ld.shared.b32 %0, [%1];" : "=r"(v) : "r"(a));
    return v;
}
__device__ __forceinline__ void mma16816(float* c, const uint32_t* a, const uint32_t* b) {
    asm volatile(
        "mma.sync.aligned.m16n8k16.row.col.f32.f16.f16.f32 "
        "{%0,%1,%2,%3}, {%4,%5,%6,%7}, {%8,%9}, {%0,%1,%2,%3};"
        : "+f"(c[0]), "+f"(c[1]), "+f"(c[2]), "+f"(c[3])
        : "r"(a[0]), "r"(a[1]), "r"(a[2]), "r"(a[3]), "r"(b[0]), "r"(b[1]));
}

// ---- prep: feats f32 -> f16 ----
__global__ void prep_feats_kernel(const float* __restrict__ f) {
    size_t i = (size_t)blockIdx.x * 256 + threadIdx.x;   // 4 floats per thread
    if (i >= (size_t)NPTS * 16) return;
    float4 v = ((const float4*)f)[i];
    __half2 h0 = __floats2half2_rn(v.x, v.y);
    __half2 h1 = __floats2half2_rn(v.z, v.w);
    uint2 u;
    u.x = *(uint32_t*)&h0;
    u.y = *(uint32_t*)&h1;
    ((uint2*)g_fh)[i] = u;
}

// ---- prep: W[k][cin][cout] -> packed half2 over k-pairs, XOR-swizzled cols ----
// b-fragment LDS bank = ((nt^rl)*8 + q): conflict-free.
__global__ void prep_w_kernel(const float* __restrict__ W) {
    int i = blockIdx.x * 256 + threadIdx.x;
    if (i >= KOFF * 32 * 64) return;
    int k   = i >> 11;
    int rem = i & 2047;
    int kp  = rem >> 6;      // k' = cin/2
    int n   = rem & 63;
    const float* wk = W + k * 4096;
    __half2 h = __floats2half2_rn(wk[(2 * kp) * 64 + n], wk[(2 * kp + 1) * 64 + n]);
    g_wt[k * 2048 + kp * 64 + (n ^ ((kp & 3) << 3))] = *(uint32_t*)&h;
}

// ---- main conv layer ----
__global__ void __launch_bounds__(NTH, 2)
conv_layer_kernel(const float* __restrict__ feats,   // residual (f32)
                  const float* __restrict__ bias,
                  const float* __restrict__ alpha,
                  const int*   __restrict__ nbr,
                  float*       __restrict__ out_final,
                  int layer)
{
    extern __shared__ __align__(16) char smem[];
    const int tid = threadIdx.x;
    const int tile_base = blockIdx.x * TILE;
    const uint32_t sb = smem_u32(smem);

    const __half* in = (layer == 0) ? (const __half*)g_fh : (const __half*)g_xh;

    // stage neighbor indices + bias
    int* nbr_s = (int*)smem;
    {
        int vr = NPTS - tile_base; if (vr > TILE) vr = TILE;
        int total = vr * KOFF;
        const int* ng = nbr + (size_t)tile_base * KOFF;
        for (int f = tid; f < TILE * KOFF; f += NTH) nbr_s[f] = (f < total) ? ng[f] : -1;
        if (tid < 64) ((float*)(smem + SM_BIAS))[tid] = bias[tid];
    }
    __syncthreads();

    const int row_g = tid >> 1;      // gather row 0..127
    const int halfg = tid & 1;       // which 4-chunk half of the 128B row

    auto prefetch = [&](int buf, int k) {
        // B: linear 8KB copy of packed W[k] (512 x 16B)
        const uint32_t* ws = g_wt + k * 2048;
        uint32_t bd = sb + SM_B + buf * 8192;
        #pragma unroll
        for (int i = 0; i < 2; i++) {
            int e = tid + i * NTH;
            cp16(bd + e * 16, ws + e * 4);
        }
        // A: gather 128 rows x 128B (f16), XOR-swizzled 16B chunks, zero-fill invalid
        int idx = nbr_s[row_g * KOFF + k];
        const __half* sr = in + (size_t)(idx < 0 ? 0 : idx) * 64;
        uint32_t ad = sb + SM_A + buf * 16384 + row_g * 128;
        unsigned sz = (idx >= 0) ? 16u : 0u;
        int r7 = row_g & 7;
        #pragma unroll
        for (int j = 0; j < 4; j++) {
            int c = halfg * 4 + j;
            cp16z(ad + ((c ^ r7) << 4), sr + c * 8, sz);
        }
        asm volatile("cp.async.commit_group;" ::: "memory");
    };

    const int lane = tid & 31, w = tid >> 5;
    const int wm = w & 3, wn = w >> 2;      // warp grid 4(m) x 2(n); warp tile 32x32
    const int q = lane >> 2, rl = lane & 3;

    float acc[2][4][4];
    #pragma unroll
    for (int i = 0; i < 2; i++)
        #pragma unroll
        for (int j = 0; j < 4; j++)
            #pragma unroll
            for (int l = 0; l < 4; l++) acc[i][j][l] = 0.f;

    // A per-thread row byte bases (rows r and r+8 share swizzle key q)
    uint32_t arow[2];
    #pragma unroll
    for (int mt = 0; mt < 2; mt++) {
        int r = wm * 32 + mt * 16 + q;
        arow[mt] = (uint32_t)(r * 128 + rl * 4);
    }
    // B per-thread base: k'-row rl (256B rows), col word (wn*32+q)
    const uint32_t bbase = (uint32_t)(rl * 256 + (wn * 32 + q) * 4);

    prefetch(0, 0);

    #pragma unroll 1
    for (int k = 0; k < KOFF; k++) {
        const int cur = k & 1;
        if (k + 1 < KOFF) {
            prefetch(1 - cur, k + 1);
            asm volatile("cp.async.wait_group 1;" ::: "memory");
        } else {
            asm volatile("cp.async.wait_group 0;" ::: "memory");
        }
        __syncthreads();

        const uint32_t Ab = sb + SM_A + cur * 16384;
        const uint32_t Bb = sb + SM_B + cur * 8192 + bbase;
        #pragma unroll
        for (int kc = 0; kc < 4; kc++) {
            const uint32_t o0 = (uint32_t)(((kc * 2)     ^ q) << 4);
            const uint32_t o1 = (uint32_t)(((kc * 2 + 1) ^ q) << 4);
            uint32_t a[2][4];
            #pragma unroll
            for (int mt = 0; mt < 2; mt++) {
                uint32_t ra = Ab + arow[mt];
                a[mt][0] = lds_u(ra + o0);           // row q,   k lo-half
                a[mt][1] = lds_u(ra + 1024 + o0);    // row q+8, k lo-half
                a[mt][2] = lds_u(ra + o1);           // row q,   k hi-half
                a[mt][3] = lds_u(ra + 1024 + o1);    // row q+8, k hi-half
            }
            uint32_t b[4][2];
            const uint32_t bk = Bb + (uint32_t)(kc * 2048);
            #pragma unroll
            for (int nt = 0; nt < 4; nt++) {
                uint32_t co = (uint32_t)((nt ^ rl) << 5);
                b[nt][0] = lds_u(bk + co);           // k' = kc*8 + rl
                b[nt][1] = lds_u(bk + 1024 + co);    // k' = kc*8 + rl + 4
            }
            #pragma unroll
            for (int mt = 0; mt < 2; mt++)
                #pragma unroll
                for (int nt = 0; nt < 4; nt++)
                    mma16816(acc[mt][nt], a[mt], b[nt]);
        }
        __syncthreads();
    }

    // ---- epilogue ----
    const float av = alpha[0];
    const float* bs = (const float*)(smem + SM_BIAS);
    #pragma unroll
    for (int mt = 0; mt < 2; mt++) {
        #pragma unroll
        for (int hh = 0; hh < 2; hh++) {
            int np = tile_base + wm * 32 + mt * 16 + q + hh * 8;
            if (np < NPTS) {
                #pragma unroll
                for (int nt = 0; nt < 4; nt++) {
                    int cc = wn * 32 + nt * 8 + 2 * rl;
                    float v0 = acc[mt][nt][hh * 2 + 0] + bs[cc];
                    float v1 = acc[mt][nt][hh * 2 + 1] + bs[cc + 1];
                    if (layer == 0) {
                        v0 = v0 >= 0.f ? v0 : av * v0;
                        v1 = v1 >= 0.f ? v1 : av * v1;
                        __half2 h = __floats2half2_rn(v0, v1);
                        *(uint32_t*)(g_xh + (size_t)np * 64 + cc) = *(uint32_t*)&h;
                    } else {
                        const float* frow = feats + (size_t)np * 64;
                        v0 += frow[cc];
                        v1 += frow[cc + 1];
                        v0 = v0 >= 0.f ? v0 : av * v0;
                        v1 = v1 >= 0.f ? v1 : av * v1;
                        float2 vv; vv.x = v0; vv.y = v1;
                        *(float2*)(out_final + (size_t)np * 64 + cc) = vv;
                    }
                }
            }
        }
    }
}

// ---- launch ----
extern "C" void kernel_launch(void* const* d_in, const int* in_sizes, int n_in,
                              void* d_out, int out_size)
{
    const float* feats = (const float*)d_in[0];
    const float* W1    = (const float*)d_in[1];
    const float* b1    = (const float*)d_in[2];
    const float* a1    = (const float*)d_in[3];
    const float* W2    = (const float*)d_in[4];
    const float* b2    = (const float*)d_in[5];
    const float* a2    = (const float*)d_in[6];
    const int*   nbr   = (const int*)d_in[7];
    float* out = (float*)d_out;

    cudaFuncSetAttribute(conv_layer_kernel, cudaFuncAttributeMaxDynamicSharedMemorySize, SM_TOTAL);

    const int ntiles = (NPTS + TILE - 1) / TILE;
    const int prep_w_blocks = (KOFF * 32 * 64 + 255) / 256;
    const int prep_f_blocks = (int)(((size_t)NPTS * 16 + 255) / 256);

    prep_feats_kernel<<<prep_f_blocks, 256>>>(feats);
    prep_w_kernel<<<prep_w_blocks, 256>>>(W1);
    conv_layer_kernel<<<ntiles, NTH, SM_TOTAL>>>(feats, b1, a1, nbr, out, 0);
    prep_w_kernel<<<prep_w_blocks, 256>>>(W2);
    conv_layer_kernel<<<ntiles, NTH, SM_TOTAL>>>(feats, b2, a2, nbr, out, 1);
}

// round 7
// speedup vs baseline: 2.1253x; 1.0846x over previous
#include <cuda_runtime.h>
#include <cuda_fp16.h>
#include <cstdint>

#define NPTS 500000
#define KOFF 27
#define TILE 256
#define NTH  256

// ---- shared memory layout (bytes) ----
#define SM_NBR  0            // 256*27*4 = 27648
#define SM_B    27648        // 2 * 8192  -> 44032
#define SM_A    44032        // 2 * 32768 -> 109568
#define SM_BIAS 109568       // 256
#define SM_TOTAL 109824

// ---- device scratch (no allocations allowed) ----
static __device__ __align__(16) __half g_xh[(size_t)NPTS * 64];  // layer-1 activations (f16)
static __device__ __align__(16) __half g_fh[(size_t)NPTS * 64];  // feats converted to f16
static __device__ uint32_t g_wt[KOFF * 32 * 64];                 // W packed half2(k,k+1), swizzled

// ---- helpers ----
__device__ __forceinline__ uint32_t smem_u32(const void* p) {
    uint32_t a;
    asm("{ .reg .u64 t; cvta.to.shared.u64 t, %1; cvt.u32.u64 %0, t; }" : "=r"(a) : "l"(p));
    return a;
}
__device__ __forceinline__ void cp16(uint32_t d, const void* s) {
    asm volatile("cp.async.cg.shared.global [%0], [%1], 16;" :: "r"(d), "l"(s) : "memory");
}
__device__ __forceinline__ void cp16z(uint32_t d, const void* s, unsigned sz) {
    asm volatile("cp.async.cg.shared.global [%0], [%1], 16, %2;" :: "r"(d), "l"(s), "r"(sz) : "memory");
}
__device__ __forceinline__ uint32_t lds_u(uint32_t a) {
    uint32_t v;
    asm volatile("ld.shared.b32 %0, [%1];" : "=r"(v) : "r"(a));
    return v;
}
__device__ __forceinline__ void mma16816(float* c, const uint32_t* a, const uint32_t* b) {
    asm volatile(
        "mma.sync.aligned.m16n8k16.row.col.f32.f16.f16.f32 "
        "{%0,%1,%2,%3}, {%4,%5,%6,%7}, {%8,%9}, {%0,%1,%2,%3};"
        : "+f"(c[0]), "+f"(c[1]), "+f"(c[2]), "+f"(c[3])
        : "r"(a[0]), "r"(a[1]), "r"(a[2]), "r"(a[3]), "r"(b[0]), "r"(b[1]));
}

// ---- prep: feats f32 -> f16 ----
__global__ void prep_feats_kernel(const float* __restrict__ f) {
    size_t i = (size_t)blockIdx.x * 256 + threadIdx.x;   // 4 floats per thread
    if (i >= (size_t)NPTS * 16) return;
    float4 v = ((const float4*)f)[i];
    __half2 h0 = __floats2half2_rn(v.x, v.y);
    __half2 h1 = __floats2half2_rn(v.z, v.w);
    uint2 u;
    u.x = *(uint32_t*)&h0;
    u.y = *(uint32_t*)&h1;
    ((uint2*)g_fh)[i] = u;
}

// ---- prep: W[k][cin][cout] -> packed half2 over k-pairs, XOR-swizzled cols ----
__global__ void prep_w_kernel(const float* __restrict__ W) {
    int i = blockIdx.x * 256 + threadIdx.x;
    if (i >= KOFF * 32 * 64) return;
    int k   = i >> 11;
    int rem = i & 2047;
    int kp  = rem >> 6;      // k' = cin/2
    int n   = rem & 63;
    const float* wk = W + k * 4096;
    __half2 h = __floats2half2_rn(wk[(2 * kp) * 64 + n], wk[(2 * kp + 1) * 64 + n]);
    g_wt[k * 2048 + kp * 64 + (n ^ ((kp & 3) << 3))] = *(uint32_t*)&h;
}

// ---- main conv layer: 256-point tile, 8 warps, warp tile 64(m) x 32(n) ----
__global__ void __launch_bounds__(NTH, 2)
conv_layer_kernel(const float* __restrict__ feats,   // residual (f32)
                  const float* __restrict__ bias,
                  const float* __restrict__ alpha,
                  const int*   __restrict__ nbr,
                  float*       __restrict__ out_final,
                  int layer)
{
    extern __shared__ __align__(16) char smem[];
    const int tid = threadIdx.x;
    const int tile_base = blockIdx.x * TILE;
    const uint32_t sb = smem_u32(smem);

    const __half* in = (layer == 0) ? (const __half*)g_fh : (const __half*)g_xh;

    // stage neighbor indices + bias
    int* nbr_s = (int*)smem;
    {
        int vr = NPTS - tile_base; if (vr > TILE) vr = TILE;
        int total = vr * KOFF;
        const int* ng = nbr + (size_t)tile_base * KOFF;
        #pragma unroll 1
        for (int f = tid; f < TILE * KOFF; f += NTH) nbr_s[f] = (f < total) ? ng[f] : -1;
        if (tid < 64) ((float*)(smem + SM_BIAS))[tid] = bias[tid];
    }
    __syncthreads();

    const int r7 = tid & 7;

    auto prefetch = [&](int buf, int k) {
        // B: linear 8KB copy of packed W[k] (512 x 16B)
        const uint32_t* ws = g_wt + k * 2048;
        uint32_t bd = sb + SM_B + buf * 8192;
        #pragma unroll
        for (int i = 0; i < 2; i++) {
            int e = tid + i * NTH;
            cp16(bd + e * 16, ws + e * 4);
        }
        // A: gather 256 rows x 128B (f16): 1 row/thread, 8 x 16B XOR-swizzled
        int idx = nbr_s[tid * KOFF + k];
        const __half* sr = in + (size_t)(idx < 0 ? 0 : idx) * 64;
        uint32_t ad = sb + SM_A + buf * 32768 + tid * 128;
        unsigned sz = (idx >= 0) ? 16u : 0u;
        #pragma unroll
        for (int c = 0; c < 8; c++) {
            cp16z(ad + ((c ^ r7) << 4), sr + c * 8, sz);
        }
        asm volatile("cp.async.commit_group;" ::: "memory");
    };

    const int lane = tid & 31, w = tid >> 5;
    const int wm = w & 3, wn = w >> 2;      // warp grid 4(m) x 2(n); warp tile 64x32
    const int q = lane >> 2, rl = lane & 3;

    float acc[4][4][4];
    #pragma unroll
    for (int i = 0; i < 4; i++)
        #pragma unroll
        for (int j = 0; j < 4; j++)
            #pragma unroll
            for (int l = 0; l < 4; l++) acc[i][j][l] = 0.f;

    // A per-thread row byte bases: rows wm*64 + mt*16 + q (+8)
    const uint32_t abase0 = (uint32_t)((wm * 64 + q) * 128 + rl * 4);
    // B per-thread base: k'-row rl (256B rows), col word (wn*32+q)
    const uint32_t bbase = (uint32_t)(rl * 256 + (wn * 32 + q) * 4);

    prefetch(0, 0);

    #pragma unroll 1
    for (int k = 0; k < KOFF; k++) {
        const int cur = k & 1;
        if (k + 1 < KOFF) {
            prefetch(1 - cur, k + 1);
            asm volatile("cp.async.wait_group 1;" ::: "memory");
        } else {
            asm volatile("cp.async.wait_group 0;" ::: "memory");
        }
        __syncthreads();

        const uint32_t Ab = sb + SM_A + cur * 32768 + abase0;
        const uint32_t Bb = sb + SM_B + cur * 8192 + bbase;
        #pragma unroll
        for (int kc = 0; kc < 4; kc++) {
            const uint32_t o0 = (uint32_t)(((kc * 2)     ^ q) << 4);
            const uint32_t o1 = (uint32_t)(((kc * 2 + 1) ^ q) << 4);
            // B fragments first (live across mt loop): k' rows kc*8+rl, +4
            uint32_t b[4][2];
            const uint32_t bk = Bb + (uint32_t)(kc * 2048);
            #pragma unroll
            for (int nt = 0; nt < 4; nt++) {
                uint32_t co = (uint32_t)((nt ^ rl) << 5);
                b[nt][0] = lds_u(bk + co);
                b[nt][1] = lds_u(bk + 1024 + co);
            }
            // A fragments per mt, consumed immediately (short live range)
            #pragma unroll
            for (int mt = 0; mt < 4; mt++) {
                uint32_t ra = Ab + (uint32_t)(mt * 16 * 128);
                uint32_t a[4];
                a[0] = lds_u(ra + o0);           // row q,   k lo-half
                a[1] = lds_u(ra + 1024 + o0);    // row q+8, k lo-half
                a[2] = lds_u(ra + o1);           // row q,   k hi-half
                a[3] = lds_u(ra + 1024 + o1);    // row q+8, k hi-half
                #pragma unroll
                for (int nt = 0; nt < 4; nt++)
                    mma16816(acc[mt][nt], a, b[nt]);
            }
        }
        __syncthreads();
    }

    // ---- epilogue ----
    const float av = alpha[0];
    const float* bs = (const float*)(smem + SM_BIAS);
    #pragma unroll
    for (int mt = 0; mt < 4; mt++) {
        #pragma unroll
        for (int hh = 0; hh < 2; hh++) {
            int np = tile_base + wm * 64 + mt * 16 + q + hh * 8;
            if (np < NPTS) {
                #pragma unroll
                for (int nt = 0; nt < 4; nt++) {
                    int cc = wn * 32 + nt * 8 + 2 * rl;
                    float v0 = acc[mt][nt][hh * 2 + 0] + bs[cc];
                    float v1 = acc[mt][nt][hh * 2 + 1] + bs[cc + 1];
                    if (layer == 0) {
                        v0 = v0 >= 0.f ? v0 : av * v0;
                        v1 = v1 >= 0.f ? v1 : av * v1;
                        __half2 h = __floats2half2_rn(v0, v1);
                        *(uint32_t*)(g_xh + (size_t)np * 64 + cc) = *(uint32_t*)&h;
                    } else {
                        const float* frow = feats + (size_t)np * 64;
                        v0 += frow[cc];
                        v1 += frow[cc + 1];
                        v0 = v0 >= 0.f ? v0 : av * v0;
                        v1 = v1 >= 0.f ? v1 : av * v1;
                        float2 vv; vv.x = v0; vv.y = v1;
                        *(float2*)(out_final + (size_t)np * 64 + cc) = vv;
                    }
                }
            }
        }
    }
}

// ---- launch ----
extern "C" void kernel_launch(void* const* d_in, const int* in_sizes, int n_in,
                              void* d_out, int out_size)
{
    const float* feats = (const float*)d_in[0];
    const float* W1    = (const float*)d_in[1];
    const float* b1    = (const float*)d_in[2];
    const float* a1    = (const float*)d_in[3];
    const float* W2    = (const float*)d_in[4];
    const float* b2    = (const float*)d_in[5];
    const float* a2    = (const float*)d_in[6];
    const int*   nbr   = (const int*)d_in[7];
    float* out = (float*)d_out;

    cudaFuncSetAttribute(conv_layer_kernel, cudaFuncAttributeMaxDynamicSharedMemorySize, SM_TOTAL);

    const int ntiles = (NPTS + TILE - 1) / TILE;
    const int prep_w_blocks = (KOFF * 32 * 64 + 255) / 256;
    const int prep_f_blocks = (int)(((size_t)NPTS * 16 + 255) / 256);

    prep_feats_kernel<<<prep_f_blocks, 256>>>(feats);
    prep_w_kernel<<<prep_w_blocks, 256>>>(W1);
    conv_layer_kernel<<<ntiles, NTH, SM_TOTAL>>>(feats, b1, a1, nbr, out, 0);
    prep_w_kernel<<<prep_w_blocks, 256>>>(W2);
    conv_layer_kernel<<<ntiles, NTH, SM_TOTAL>>>(feats, b2, a2, nbr, out, 1);
}